// round 1
// baseline (speedup 1.0000x reference)
#include <cuda_runtime.h>

#define SEQ 2048
#define DIM 4096
#define NH  32
#define NKV 8
#define HD  128

// ---------------- scratch (device globals: no allocation allowed) ----------------
__device__ float g_q[(size_t)SEQ * DIM];          // [S][H][HD]
__device__ float g_k[(size_t)SEQ * NKV * HD];     // [S][KV][HD]
__device__ float g_v[(size_t)SEQ * NKV * HD];     // [S][KV][HD]
__device__ float g_att[(size_t)SEQ * DIM];        // [S][H][HD]

// ---------------- NT GEMM: C[M,N] = A[M,K] * B[N,K]^T ----------------
// 128x128 tile, BK=16, 256 threads, 8x8 micro-tile.
__global__ __launch_bounds__(256) void gemm_nt(const float* __restrict__ A,
                                               const float* __restrict__ B,
                                               float* __restrict__ C,
                                               int M, int N, int K)
{
    const int BM = 128, BN = 128, BK = 16;
    __shared__ float As[BK][BM + 4];
    __shared__ float Bs[BK][BN + 4];

    int tid = threadIdx.x;
    int m0 = blockIdx.y * BM;
    int n0 = blockIdx.x * BN;
    int tx = tid & 15;        // 0..15 -> N direction
    int ty = tid >> 4;        // 0..15 -> M direction
    int lr = tid >> 2;        // 0..63  loader row
    int lc = (tid & 3) << 2;  // 0,4,8,12 loader col (k)

    float acc[8][8];
#pragma unroll
    for (int i = 0; i < 8; i++)
#pragma unroll
        for (int j = 0; j < 8; j++) acc[i][j] = 0.0f;

    const float* Ap = A + (size_t)(m0 + lr) * K + lc;
    const float* Bp = B + (size_t)(n0 + lr) * K + lc;

    for (int k0 = 0; k0 < K; k0 += BK) {
#pragma unroll
        for (int rr = 0; rr < 2; rr++) {
            float4 a = *(const float4*)(Ap + (size_t)rr * 64 * K + k0);
            int r = lr + rr * 64;
            As[lc + 0][r] = a.x; As[lc + 1][r] = a.y;
            As[lc + 2][r] = a.z; As[lc + 3][r] = a.w;
            float4 b = *(const float4*)(Bp + (size_t)rr * 64 * K + k0);
            Bs[lc + 0][r] = b.x; Bs[lc + 1][r] = b.y;
            Bs[lc + 2][r] = b.z; Bs[lc + 3][r] = b.w;
        }
        __syncthreads();
#pragma unroll
        for (int kk = 0; kk < BK; kk++) {
            float a[8], b[8];
            *(float4*)(a)     = *(const float4*)&As[kk][ty * 8];
            *(float4*)(a + 4) = *(const float4*)&As[kk][ty * 8 + 4];
            *(float4*)(b)     = *(const float4*)&Bs[kk][tx * 8];
            *(float4*)(b + 4) = *(const float4*)&Bs[kk][tx * 8 + 4];
#pragma unroll
            for (int i = 0; i < 8; i++)
#pragma unroll
                for (int j = 0; j < 8; j++)
                    acc[i][j] = fmaf(a[i], b[j], acc[i][j]);
        }
        __syncthreads();
    }

#pragma unroll
    for (int i = 0; i < 8; i++) {
        int row = m0 + ty * 8 + i;
        float4 c0 = make_float4(acc[i][0], acc[i][1], acc[i][2], acc[i][3]);
        float4 c1 = make_float4(acc[i][4], acc[i][5], acc[i][6], acc[i][7]);
        *(float4*)&C[(size_t)row * N + n0 + tx * 8]     = c0;
        *(float4*)&C[(size_t)row * N + n0 + tx * 8 + 4] = c1;
    }
}

// ---------------- RoPE (interleaved pairs) ----------------
__global__ void rope_kernel(float* __restrict__ t, const float* __restrict__ cs,
                            const float* __restrict__ sn, int nh, int total)
{
    int idx = blockIdx.x * blockDim.x + threadIdx.x;
    if (idx >= total) return;
    int pr = idx & 63;
    int hh = (idx >> 6) % nh;
    int ss = idx / (64 * nh);
    float c  = cs[ss * 64 + pr];
    float si = sn[ss * 64 + pr];
    float2* p = (float2*)(t + ((size_t)ss * nh + hh) * HD + pr * 2);
    float2 ri = *p;
    float2 o;
    o.x = ri.x * c - ri.y * si;
    o.y = ri.x * si + ri.y * c;
    *p = o;
}

// ---------------- Flash attention, causal, GQA ----------------
// Grid: (S/64, H). 256 threads. BM=BN=64, 4x4 score micro-tile, 4x8 O micro-tile.
__global__ __launch_bounds__(256) void attn_kernel(const float* __restrict__ Q,
                                                   const float* __restrict__ Kg,
                                                   const float* __restrict__ Vg,
                                                   float* __restrict__ O)
{
    extern __shared__ float sm[];
    float* Qs = sm;                    // 64 x 129
    float* Ks = Qs + 64 * 129;         // 64 x 129
    float* Vs = Ks + 64 * 129;         // 64 x 132
    float* Ps = Vs + 64 * 132;         // 64 x 65

    int tid = threadIdx.x;
    int tx = tid & 15;   // key cols / hd cols
    int ty = tid >> 4;   // query rows
    int qt = blockIdx.x;
    int h  = blockIdx.y;
    int qm0 = qt * 64;
    int kvh = h >> 2;    // GQA: rep = 4
    const float scale = 0.08838834764831845f; // 1/sqrt(128)

    // Q tile (pre-scaled)
    for (int i = tid; i < 64 * 128; i += 256) {
        int r = i >> 7, c = i & 127;
        Qs[r * 129 + c] = Q[((size_t)(qm0 + r) * NH + h) * HD + c] * scale;
    }

    float m_i[4], l_i[4], o[4][8];
#pragma unroll
    for (int i = 0; i < 4; i++) {
        m_i[i] = -1e30f; l_i[i] = 0.0f;
#pragma unroll
        for (int j = 0; j < 8; j++) o[i][j] = 0.0f;
    }

    for (int kt = 0; kt <= qt; kt++) {
        int kn0 = kt * 64;
        __syncthreads();   // also covers Q-load -> score read on first iter
        for (int i = tid; i < 64 * 128; i += 256) {
            int r = i >> 7, c = i & 127;
            Ks[r * 129 + c] = Kg[((size_t)(kn0 + r) * NKV + kvh) * HD + c];
        }
        for (int i = tid; i < 64 * 32; i += 256) {
            int r = i >> 5, c4 = (i & 31) << 2;
            *(float4*)&Vs[r * 132 + c4] =
                *(const float4*)&Vg[((size_t)(kn0 + r) * NKV + kvh) * HD + c4];
        }
        __syncthreads();

        // scores 4x4
        float s[4][4];
#pragma unroll
        for (int i = 0; i < 4; i++)
#pragma unroll
            for (int j = 0; j < 4; j++) s[i][j] = 0.0f;

#pragma unroll 4
        for (int kk = 0; kk < 128; kk++) {
            float qv[4], kv[4];
#pragma unroll
            for (int i = 0; i < 4; i++) qv[i] = Qs[(ty * 4 + i) * 129 + kk];
#pragma unroll
            for (int j = 0; j < 4; j++) kv[j] = Ks[(tx * 4 + j) * 129 + kk];
#pragma unroll
            for (int i = 0; i < 4; i++)
#pragma unroll
                for (int j = 0; j < 4; j++)
                    s[i][j] = fmaf(qv[i], kv[j], s[i][j]);
        }

        if (kt == qt) {  // diagonal tile: causal mask
#pragma unroll
            for (int i = 0; i < 4; i++)
#pragma unroll
                for (int j = 0; j < 4; j++)
                    if (tx * 4 + j > ty * 4 + i) s[i][j] = -1e30f;
        }

        // online softmax per row (rows shared by 16 contiguous lanes)
#pragma unroll
        for (int i = 0; i < 4; i++) {
            float rm = fmaxf(fmaxf(s[i][0], s[i][1]), fmaxf(s[i][2], s[i][3]));
#pragma unroll
            for (int off = 1; off < 16; off <<= 1)
                rm = fmaxf(rm, __shfl_xor_sync(0xffffffffu, rm, off));
            float mn  = fmaxf(m_i[i], rm);
            float fac = __expf(m_i[i] - mn);
            float rs  = 0.0f;
#pragma unroll
            for (int j = 0; j < 4; j++) {
                s[i][j] = __expf(s[i][j] - mn);
                rs += s[i][j];
            }
#pragma unroll
            for (int off = 1; off < 16; off <<= 1)
                rs += __shfl_xor_sync(0xffffffffu, rs, off);
            l_i[i] = l_i[i] * fac + rs;
            m_i[i] = mn;
#pragma unroll
            for (int j = 0; j < 8; j++) o[i][j] *= fac;
#pragma unroll
            for (int j = 0; j < 4; j++)
                Ps[(ty * 4 + i) * 65 + tx * 4 + j] = s[i][j];
        }
        __syncthreads();

        // O += P @ V  (4 rows x 8 cols per thread)
#pragma unroll 2
        for (int kk = 0; kk < 64; kk++) {
            float pv[4];
#pragma unroll
            for (int i = 0; i < 4; i++) pv[i] = Ps[(ty * 4 + i) * 65 + kk];
            float4 v0 = *(const float4*)&Vs[kk * 132 + tx * 8];
            float4 v1 = *(const float4*)&Vs[kk * 132 + tx * 8 + 4];
#pragma unroll
            for (int i = 0; i < 4; i++) {
                o[i][0] = fmaf(pv[i], v0.x, o[i][0]);
                o[i][1] = fmaf(pv[i], v0.y, o[i][1]);
                o[i][2] = fmaf(pv[i], v0.z, o[i][2]);
                o[i][3] = fmaf(pv[i], v0.w, o[i][3]);
                o[i][4] = fmaf(pv[i], v1.x, o[i][4]);
                o[i][5] = fmaf(pv[i], v1.y, o[i][5]);
                o[i][6] = fmaf(pv[i], v1.z, o[i][6]);
                o[i][7] = fmaf(pv[i], v1.w, o[i][7]);
            }
        }
    }

#pragma unroll
    for (int i = 0; i < 4; i++) {
        float inv = 1.0f / l_i[i];
        int qr = qm0 + ty * 4 + i;
        float4 r0 = make_float4(o[i][0] * inv, o[i][1] * inv, o[i][2] * inv, o[i][3] * inv);
        float4 r1 = make_float4(o[i][4] * inv, o[i][5] * inv, o[i][6] * inv, o[i][7] * inv);
        *(float4*)&O[((size_t)qr * NH + h) * HD + tx * 8]     = r0;
        *(float4*)&O[((size_t)qr * NH + h) * HD + tx * 8 + 4] = r1;
    }
}

// ---------------- launch ----------------
extern "C" void kernel_launch(void* const* d_in, const int* in_sizes, int n_in,
                              void* d_out, int out_size)
{
    const float* x  = (const float*)d_in[0];
    const float* wq = (const float*)d_in[1];
    const float* wk = (const float*)d_in[2];
    const float* wv = (const float*)d_in[3];
    const float* wo = (const float*)d_in[4];
    const float* fc = (const float*)d_in[5];
    const float* fs = (const float*)d_in[6];
    // d_in[7] = mask (causal, implemented analytically)
    float* out = (float*)d_out;

    float *q, *k, *v, *att;
    cudaGetSymbolAddress((void**)&q,   g_q);
    cudaGetSymbolAddress((void**)&k,   g_k);
    cudaGetSymbolAddress((void**)&v,   g_v);
    cudaGetSymbolAddress((void**)&att, g_att);

    dim3 blk(256);
    // QKV projections
    gemm_nt<<<dim3(DIM / 128, SEQ / 128), blk>>>(x, wq, q, SEQ, DIM, DIM);
    gemm_nt<<<dim3(NKV * HD / 128, SEQ / 128), blk>>>(x, wk, k, SEQ, NKV * HD, DIM);
    gemm_nt<<<dim3(NKV * HD / 128, SEQ / 128), blk>>>(x, wv, v, SEQ, NKV * HD, DIM);
    // RoPE
    rope_kernel<<<(SEQ * NH * 64 + 255) / 256, 256>>>(q, fc, fs, NH, SEQ * NH * 64);
    rope_kernel<<<(SEQ * NKV * 64 + 255) / 256, 256>>>(k, fc, fs, NKV, SEQ * NKV * 64);
    // Attention
    int shmem = (64 * 129 * 2 + 64 * 132 + 64 * 65) * (int)sizeof(float);
    cudaFuncSetAttribute(attn_kernel, cudaFuncAttributeMaxDynamicSharedMemorySize, shmem);
    attn_kernel<<<dim3(SEQ / 64, NH), blk, shmem>>>(q, k, v, att);
    // Output projection
    gemm_nt<<<dim3(DIM / 128, SEQ / 128), blk>>>(att, wo, out, SEQ, DIM, DIM);
}

// round 2
// speedup vs baseline: 2.0265x; 2.0265x over previous
#include <cuda_runtime.h>
#include <cstdint>

#define SEQ 2048
#define DIM 4096
#define NH  32
#define NKV 8
#define HD  128

// ---------------- scratch (device globals: no allocation allowed) ----------------
__device__ float g_q[(size_t)SEQ * DIM];          // [S][H][HD]
__device__ float g_k[(size_t)SEQ * NKV * HD];     // [S][KV][HD]
__device__ float g_v[(size_t)SEQ * NKV * HD];     // [S][KV][HD]
__device__ float g_att[(size_t)SEQ * DIM];        // [S][H][HD]

__device__ __forceinline__ uint32_t cvt_tf32(float x) {
    uint32_t r;
    asm("cvt.rna.tf32.f32 %0, %1;" : "=r"(r) : "f"(x));
    return r;
}

// ---------------- TF32 tensor-core NT GEMM: C[M,N] = A[M,K] * B[N,K]^T ------------
// 128x128x32 tile, 256 threads (8 warps, 2x4), warp tile 64x32, mma m16n8k8 tf32.
// Double-buffered smem, stride-36 padding (conflict-free ldmatrix).
#define SA 36
#define BUFE (2 * 128 * SA)   // uint32 elements per buffer (A tile + B tile)

__global__ __launch_bounds__(256, 1) void gemm_tf32(const float* __restrict__ A,
                                                    const float* __restrict__ B,
                                                    float* __restrict__ C,
                                                    int M, int N, int K)
{
    extern __shared__ uint32_t sh[];
    int tid = threadIdx.x;
    int wid = tid >> 5, lane = tid & 31;
    int warp_m = wid >> 2, warp_n = wid & 3;
    int m0 = blockIdx.y * 128, n0 = blockIdx.x * 128;

    // global loaders: 4 float4 rows per thread per tile
    int lr = tid >> 3;           // 0..31
    int lc = (tid & 7) * 4;      // 0..28
    const float* Aq = A + (size_t)(m0 + lr) * K + lc;
    const float* Bq = B + (size_t)(n0 + lr) * K + lc;

    float ra[4][4], rb[4][4];

    uint32_t shbase = (uint32_t)__cvta_generic_to_shared(sh);

    // ldmatrix fragment addresses (lane-mapped, buffer 0, ks 0)
    uint32_t a_addr[4], b_addr[4];
    {
        int la = lane & 15;
        int ahi = (lane >> 4) & 1;                // k-offset 0 or 4
#pragma unroll
        for (int mi = 0; mi < 4; mi++) {
            int r = warp_m * 64 + mi * 16 + la;
            a_addr[mi] = shbase + (uint32_t)((r * SA + ahi * 4) * 4);
        }
        int lb = lane & 7;
        int bhi = (lane >> 3) & 1;                // k-offset 0 or 4 (lanes 0-15 used)
#pragma unroll
        for (int ni = 0; ni < 4; ni++) {
            int r = warp_n * 32 + ni * 8 + lb;
            b_addr[ni] = shbase + (uint32_t)((128 * SA + r * SA + (bhi & 1) * 4) * 4);
        }
    }

    float acc[4][4][4];
#pragma unroll
    for (int mi = 0; mi < 4; mi++)
#pragma unroll
        for (int ni = 0; ni < 4; ni++)
#pragma unroll
            for (int t = 0; t < 4; t++) acc[mi][ni][t] = 0.0f;

    const int iters = K >> 5;

    // prologue: load tile 0
#pragma unroll
    for (int rr = 0; rr < 4; rr++) {
        float4 a = *(const float4*)(Aq + (size_t)rr * 32 * K);
        ra[rr][0] = a.x; ra[rr][1] = a.y; ra[rr][2] = a.z; ra[rr][3] = a.w;
        float4 b = *(const float4*)(Bq + (size_t)rr * 32 * K);
        rb[rr][0] = b.x; rb[rr][1] = b.y; rb[rr][2] = b.z; rb[rr][3] = b.w;
    }
#pragma unroll
    for (int rr = 0; rr < 4; rr++) {
        uint32_t* As = sh;
        uint32_t* Bs = sh + 128 * SA;
        uint4 av = make_uint4(cvt_tf32(ra[rr][0]), cvt_tf32(ra[rr][1]),
                              cvt_tf32(ra[rr][2]), cvt_tf32(ra[rr][3]));
        *(uint4*)&As[(lr + 32 * rr) * SA + lc] = av;
        uint4 bv = make_uint4(cvt_tf32(rb[rr][0]), cvt_tf32(rb[rr][1]),
                              cvt_tf32(rb[rr][2]), cvt_tf32(rb[rr][3]));
        *(uint4*)&Bs[(lr + 32 * rr) * SA + lc] = bv;
    }
    __syncthreads();

    for (int it = 0; it < iters; ++it) {
        int cur = it & 1;
        // prefetch next tile from gmem
        if (it + 1 < iters) {
            int ko = (it + 1) << 5;
#pragma unroll
            for (int rr = 0; rr < 4; rr++) {
                float4 a = *(const float4*)(Aq + (size_t)rr * 32 * K + ko);
                ra[rr][0] = a.x; ra[rr][1] = a.y; ra[rr][2] = a.z; ra[rr][3] = a.w;
                float4 b = *(const float4*)(Bq + (size_t)rr * 32 * K + ko);
                rb[rr][0] = b.x; rb[rr][1] = b.y; rb[rr][2] = b.z; rb[rr][3] = b.w;
            }
        }

        // compute on current buffer
        uint32_t boff = (uint32_t)(cur * BUFE * 4);
#pragma unroll
        for (int ks = 0; ks < 4; ks++) {
            uint32_t af[4][4], bf[4][2];
#pragma unroll
            for (int mi = 0; mi < 4; mi++)
                asm volatile("ldmatrix.sync.aligned.m8n8.x4.shared.b16 {%0,%1,%2,%3}, [%4];"
                             : "=r"(af[mi][0]), "=r"(af[mi][1]), "=r"(af[mi][2]), "=r"(af[mi][3])
                             : "r"(a_addr[mi] + boff + ks * 32));
#pragma unroll
            for (int ni = 0; ni < 4; ni++)
                asm volatile("ldmatrix.sync.aligned.m8n8.x2.shared.b16 {%0,%1}, [%2];"
                             : "=r"(bf[ni][0]), "=r"(bf[ni][1])
                             : "r"(b_addr[ni] + boff + ks * 32));
#pragma unroll
            for (int mi = 0; mi < 4; mi++)
#pragma unroll
                for (int ni = 0; ni < 4; ni++)
                    asm volatile("mma.sync.aligned.m16n8k8.row.col.f32.tf32.tf32.f32 "
                                 "{%0,%1,%2,%3}, {%4,%5,%6,%7}, {%8,%9}, {%0,%1,%2,%3};"
                                 : "+f"(acc[mi][ni][0]), "+f"(acc[mi][ni][1]),
                                   "+f"(acc[mi][ni][2]), "+f"(acc[mi][ni][3])
                                 : "r"(af[mi][0]), "r"(af[mi][1]), "r"(af[mi][2]), "r"(af[mi][3]),
                                   "r"(bf[ni][0]), "r"(bf[ni][1]));
        }

        // store prefetched tile into other buffer
        if (it + 1 < iters) {
            uint32_t* As = sh + (cur ^ 1) * BUFE;
            uint32_t* Bs = As + 128 * SA;
#pragma unroll
            for (int rr = 0; rr < 4; rr++) {
                uint4 av = make_uint4(cvt_tf32(ra[rr][0]), cvt_tf32(ra[rr][1]),
                                      cvt_tf32(ra[rr][2]), cvt_tf32(ra[rr][3]));
                *(uint4*)&As[(lr + 32 * rr) * SA + lc] = av;
                uint4 bv = make_uint4(cvt_tf32(rb[rr][0]), cvt_tf32(rb[rr][1]),
                                      cvt_tf32(rb[rr][2]), cvt_tf32(rb[rr][3]));
                *(uint4*)&Bs[(lr + 32 * rr) * SA + lc] = bv;
            }
            __syncthreads();
        }
    }

    // epilogue
    int g = lane >> 2, tg = lane & 3;
#pragma unroll
    for (int mi = 0; mi < 4; mi++) {
#pragma unroll
        for (int ni = 0; ni < 4; ni++) {
            int row = m0 + warp_m * 64 + mi * 16 + g;
            int col = n0 + warp_n * 32 + ni * 8 + tg * 2;
            *(float2*)&C[(size_t)row * N + col] =
                make_float2(acc[mi][ni][0], acc[mi][ni][1]);
            *(float2*)&C[(size_t)(row + 8) * N + col] =
                make_float2(acc[mi][ni][2], acc[mi][ni][3]);
        }
    }
}

// ---------------- RoPE (interleaved pairs) ----------------
__global__ void rope_kernel(float* __restrict__ t, const float* __restrict__ cs,
                            const float* __restrict__ sn, int nh, int total)
{
    int idx = blockIdx.x * blockDim.x + threadIdx.x;
    if (idx >= total) return;
    int pr = idx & 63;
    int hh = (idx >> 6) % nh;
    int ss = idx / (64 * nh);
    float c  = cs[ss * 64 + pr];
    float si = sn[ss * 64 + pr];
    float2* p = (float2*)(t + ((size_t)ss * nh + hh) * HD + pr * 2);
    float2 ri = *p;
    float2 o;
    o.x = ri.x * c - ri.y * si;
    o.y = ri.x * si + ri.y * c;
    *p = o;
}

// ---------------- Flash attention, causal, GQA (fp32 SIMT) ----------------
__global__ __launch_bounds__(256) void attn_kernel(const float* __restrict__ Q,
                                                   const float* __restrict__ Kg,
                                                   const float* __restrict__ Vg,
                                                   float* __restrict__ O)
{
    extern __shared__ float sm[];
    float* Qs = sm;                    // 64 x 129
    float* Ks = Qs + 64 * 129;         // 64 x 129
    float* Vs = Ks + 64 * 129;         // 64 x 132
    float* Ps = Vs + 64 * 132;         // 64 x 65

    int tid = threadIdx.x;
    int tx = tid & 15;
    int ty = tid >> 4;
    int qt = blockIdx.x;
    int h  = blockIdx.y;
    int qm0 = qt * 64;
    int kvh = h >> 2;
    const float scale = 0.08838834764831845f;

    for (int i = tid; i < 64 * 128; i += 256) {
        int r = i >> 7, c = i & 127;
        Qs[r * 129 + c] = Q[((size_t)(qm0 + r) * NH + h) * HD + c] * scale;
    }

    float m_i[4], l_i[4], o[4][8];
#pragma unroll
    for (int i = 0; i < 4; i++) {
        m_i[i] = -1e30f; l_i[i] = 0.0f;
#pragma unroll
        for (int j = 0; j < 8; j++) o[i][j] = 0.0f;
    }

    for (int kt = 0; kt <= qt; kt++) {
        int kn0 = kt * 64;
        __syncthreads();
        for (int i = tid; i < 64 * 128; i += 256) {
            int r = i >> 7, c = i & 127;
            Ks[r * 129 + c] = Kg[((size_t)(kn0 + r) * NKV + kvh) * HD + c];
        }
        for (int i = tid; i < 64 * 32; i += 256) {
            int r = i >> 5, c4 = (i & 31) << 2;
            *(float4*)&Vs[r * 132 + c4] =
                *(const float4*)&Vg[((size_t)(kn0 + r) * NKV + kvh) * HD + c4];
        }
        __syncthreads();

        float s[4][4];
#pragma unroll
        for (int i = 0; i < 4; i++)
#pragma unroll
            for (int j = 0; j < 4; j++) s[i][j] = 0.0f;

#pragma unroll 4
        for (int kk = 0; kk < 128; kk++) {
            float qv[4], kv[4];
#pragma unroll
            for (int i = 0; i < 4; i++) qv[i] = Qs[(ty * 4 + i) * 129 + kk];
#pragma unroll
            for (int j = 0; j < 4; j++) kv[j] = Ks[(tx * 4 + j) * 129 + kk];
#pragma unroll
            for (int i = 0; i < 4; i++)
#pragma unroll
                for (int j = 0; j < 4; j++)
                    s[i][j] = fmaf(qv[i], kv[j], s[i][j]);
        }

        if (kt == qt) {
#pragma unroll
            for (int i = 0; i < 4; i++)
#pragma unroll
                for (int j = 0; j < 4; j++)
                    if (tx * 4 + j > ty * 4 + i) s[i][j] = -1e30f;
        }

#pragma unroll
        for (int i = 0; i < 4; i++) {
            float rm = fmaxf(fmaxf(s[i][0], s[i][1]), fmaxf(s[i][2], s[i][3]));
#pragma unroll
            for (int off = 1; off < 16; off <<= 1)
                rm = fmaxf(rm, __shfl_xor_sync(0xffffffffu, rm, off));
            float mn  = fmaxf(m_i[i], rm);
            float fac = __expf(m_i[i] - mn);
            float rs  = 0.0f;
#pragma unroll
            for (int j = 0; j < 4; j++) {
                s[i][j] = __expf(s[i][j] - mn);
                rs += s[i][j];
            }
#pragma unroll
            for (int off = 1; off < 16; off <<= 1)
                rs += __shfl_xor_sync(0xffffffffu, rs, off);
            l_i[i] = l_i[i] * fac + rs;
            m_i[i] = mn;
#pragma unroll
            for (int j = 0; j < 8; j++) o[i][j] *= fac;
#pragma unroll
            for (int j = 0; j < 4; j++)
                Ps[(ty * 4 + i) * 65 + tx * 4 + j] = s[i][j];
        }
        __syncthreads();

#pragma unroll 2
        for (int kk = 0; kk < 64; kk++) {
            float pv[4];
#pragma unroll
            for (int i = 0; i < 4; i++) pv[i] = Ps[(ty * 4 + i) * 65 + kk];
            float4 v0 = *(const float4*)&Vs[kk * 132 + tx * 8];
            float4 v1 = *(const float4*)&Vs[kk * 132 + tx * 8 + 4];
#pragma unroll
            for (int i = 0; i < 4; i++) {
                o[i][0] = fmaf(pv[i], v0.x, o[i][0]);
                o[i][1] = fmaf(pv[i], v0.y, o[i][1]);
                o[i][2] = fmaf(pv[i], v0.z, o[i][2]);
                o[i][3] = fmaf(pv[i], v0.w, o[i][3]);
                o[i][4] = fmaf(pv[i], v1.x, o[i][4]);
                o[i][5] = fmaf(pv[i], v1.y, o[i][5]);
                o[i][6] = fmaf(pv[i], v1.z, o[i][6]);
                o[i][7] = fmaf(pv[i], v1.w, o[i][7]);
            }
        }
    }

#pragma unroll
    for (int i = 0; i < 4; i++) {
        float inv = 1.0f / l_i[i];
        int qr = qm0 + ty * 4 + i;
        float4 r0 = make_float4(o[i][0] * inv, o[i][1] * inv, o[i][2] * inv, o[i][3] * inv);
        float4 r1 = make_float4(o[i][4] * inv, o[i][5] * inv, o[i][6] * inv, o[i][7] * inv);
        *(float4*)&O[((size_t)qr * NH + h) * HD + tx * 8]     = r0;
        *(float4*)&O[((size_t)qr * NH + h) * HD + tx * 8 + 4] = r1;
    }
}

// ---------------- launch ----------------
extern "C" void kernel_launch(void* const* d_in, const int* in_sizes, int n_in,
                              void* d_out, int out_size)
{
    const float* x  = (const float*)d_in[0];
    const float* wq = (const float*)d_in[1];
    const float* wk = (const float*)d_in[2];
    const float* wv = (const float*)d_in[3];
    const float* wo = (const float*)d_in[4];
    const float* fc = (const float*)d_in[5];
    const float* fs = (const float*)d_in[6];
    float* out = (float*)d_out;

    float *q, *k, *v, *att;
    cudaGetSymbolAddress((void**)&q,   g_q);
    cudaGetSymbolAddress((void**)&k,   g_k);
    cudaGetSymbolAddress((void**)&v,   g_v);
    cudaGetSymbolAddress((void**)&att, g_att);

    int gsh = 2 * BUFE * (int)sizeof(uint32_t);   // 73728 B
    cudaFuncSetAttribute(gemm_tf32, cudaFuncAttributeMaxDynamicSharedMemorySize, gsh);

    dim3 blk(256);
    gemm_tf32<<<dim3(DIM / 128, SEQ / 128), blk, gsh>>>(x, wq, q, SEQ, DIM, DIM);
    gemm_tf32<<<dim3(NKV * HD / 128, SEQ / 128), blk, gsh>>>(x, wk, k, SEQ, NKV * HD, DIM);
    gemm_tf32<<<dim3(NKV * HD / 128, SEQ / 128), blk, gsh>>>(x, wv, v, SEQ, NKV * HD, DIM);

    rope_kernel<<<(SEQ * NH * 64 + 255) / 256, 256>>>(q, fc, fs, NH, SEQ * NH * 64);
    rope_kernel<<<(SEQ * NKV * 64 + 255) / 256, 256>>>(k, fc, fs, NKV, SEQ * NKV * 64);

    int shmem = (64 * 129 * 2 + 64 * 132 + 64 * 65) * (int)sizeof(float);
    cudaFuncSetAttribute(attn_kernel, cudaFuncAttributeMaxDynamicSharedMemorySize, shmem);
    attn_kernel<<<dim3(SEQ / 64, NH), blk, shmem>>>(q, k, v, att);

    gemm_tf32<<<dim3(DIM / 128, SEQ / 128), blk, gsh>>>(att, wo, out, SEQ, DIM, DIM);
}

// round 3
// speedup vs baseline: 2.9949x; 1.4779x over previous
#include <cuda_runtime.h>
#include <cstdint>

#define SEQ 2048
#define DIM 4096
#define NH  32
#define NKV 8
#define HD  128

// ---------------- scratch (device globals: no allocation allowed) ----------------
__device__ float g_q[(size_t)SEQ * DIM];          // [S][H][HD]
__device__ float g_k[(size_t)SEQ * NKV * HD];     // [S][KV][HD]
__device__ float g_v[(size_t)SEQ * NKV * HD];     // [S][KV][HD]
__device__ float g_att[(size_t)SEQ * DIM];        // [S][H][HD]

__device__ __forceinline__ uint32_t cvt_tf32(float x) {
    uint32_t r;
    asm("cvt.rna.tf32.f32 %0, %1;" : "=r"(r) : "f"(x));
    return r;
}
__device__ __forceinline__ float tf32f(float x) {
    return __uint_as_float(cvt_tf32(x));
}
__device__ __forceinline__ void ldm4(uint32_t* r, uint32_t addr) {
    asm volatile("ldmatrix.sync.aligned.m8n8.x4.shared.b16 {%0,%1,%2,%3}, [%4];"
                 : "=r"(r[0]), "=r"(r[1]), "=r"(r[2]), "=r"(r[3]) : "r"(addr));
}
__device__ __forceinline__ void mma8(float* c, const uint32_t* a, uint32_t b0, uint32_t b1) {
    asm volatile("mma.sync.aligned.m16n8k8.row.col.f32.tf32.tf32.f32 "
                 "{%0,%1,%2,%3}, {%4,%5,%6,%7}, {%8,%9}, {%0,%1,%2,%3};"
                 : "+f"(c[0]), "+f"(c[1]), "+f"(c[2]), "+f"(c[3])
                 : "r"(a[0]), "r"(a[1]), "r"(a[2]), "r"(a[3]), "r"(b0), "r"(b1));
}

// ---------------- TF32 tensor-core NT GEMM: C[M,N] = A[M,K] * B[N,K]^T ------------
#define SA 36
#define BUFE (2 * 128 * SA)

__global__ __launch_bounds__(256, 1) void gemm_tf32(const float* __restrict__ A,
                                                    const float* __restrict__ B,
                                                    float* __restrict__ C,
                                                    int M, int N, int K)
{
    extern __shared__ uint32_t sh[];
    int tid = threadIdx.x;
    int wid = tid >> 5, lane = tid & 31;
    int warp_m = wid >> 2, warp_n = wid & 3;
    int m0 = blockIdx.y * 128, n0 = blockIdx.x * 128;

    int lr = tid >> 3;
    int lc = (tid & 7) * 4;
    const float* Aq = A + (size_t)(m0 + lr) * K + lc;
    const float* Bq = B + (size_t)(n0 + lr) * K + lc;

    float ra[4][4], rb[4][4];
    uint32_t shbase = (uint32_t)__cvta_generic_to_shared(sh);

    uint32_t a_addr[4], b_addr[4];
    {
        int la = lane & 15;
        int ahi = (lane >> 4) & 1;
#pragma unroll
        for (int mi = 0; mi < 4; mi++) {
            int r = warp_m * 64 + mi * 16 + la;
            a_addr[mi] = shbase + (uint32_t)((r * SA + ahi * 4) * 4);
        }
        int lb = lane & 7;
        int bhi = (lane >> 3) & 1;
#pragma unroll
        for (int ni = 0; ni < 4; ni++) {
            int r = warp_n * 32 + ni * 8 + lb;
            b_addr[ni] = shbase + (uint32_t)((128 * SA + r * SA + (bhi & 1) * 4) * 4);
        }
    }

    float acc[4][4][4];
#pragma unroll
    for (int mi = 0; mi < 4; mi++)
#pragma unroll
        for (int ni = 0; ni < 4; ni++)
#pragma unroll
            for (int t = 0; t < 4; t++) acc[mi][ni][t] = 0.0f;

    const int iters = K >> 5;

#pragma unroll
    for (int rr = 0; rr < 4; rr++) {
        float4 a = *(const float4*)(Aq + (size_t)rr * 32 * K);
        ra[rr][0] = a.x; ra[rr][1] = a.y; ra[rr][2] = a.z; ra[rr][3] = a.w;
        float4 b = *(const float4*)(Bq + (size_t)rr * 32 * K);
        rb[rr][0] = b.x; rb[rr][1] = b.y; rb[rr][2] = b.z; rb[rr][3] = b.w;
    }
#pragma unroll
    for (int rr = 0; rr < 4; rr++) {
        uint32_t* As = sh;
        uint32_t* Bs = sh + 128 * SA;
        uint4 av = make_uint4(cvt_tf32(ra[rr][0]), cvt_tf32(ra[rr][1]),
                              cvt_tf32(ra[rr][2]), cvt_tf32(ra[rr][3]));
        *(uint4*)&As[(lr + 32 * rr) * SA + lc] = av;
        uint4 bv = make_uint4(cvt_tf32(rb[rr][0]), cvt_tf32(rb[rr][1]),
                              cvt_tf32(rb[rr][2]), cvt_tf32(rb[rr][3]));
        *(uint4*)&Bs[(lr + 32 * rr) * SA + lc] = bv;
    }
    __syncthreads();

    for (int it = 0; it < iters; ++it) {
        int cur = it & 1;
        if (it + 1 < iters) {
            int ko = (it + 1) << 5;
#pragma unroll
            for (int rr = 0; rr < 4; rr++) {
                float4 a = *(const float4*)(Aq + (size_t)rr * 32 * K + ko);
                ra[rr][0] = a.x; ra[rr][1] = a.y; ra[rr][2] = a.z; ra[rr][3] = a.w;
                float4 b = *(const float4*)(Bq + (size_t)rr * 32 * K + ko);
                rb[rr][0] = b.x; rb[rr][1] = b.y; rb[rr][2] = b.z; rb[rr][3] = b.w;
            }
        }

        uint32_t boff = (uint32_t)(cur * BUFE * 4);
#pragma unroll
        for (int ks = 0; ks < 4; ks++) {
            uint32_t af[4][4], bf[4][2];
#pragma unroll
            for (int mi = 0; mi < 4; mi++)
                ldm4(af[mi], a_addr[mi] + boff + ks * 32);
#pragma unroll
            for (int ni = 0; ni < 4; ni++)
                asm volatile("ldmatrix.sync.aligned.m8n8.x2.shared.b16 {%0,%1}, [%2];"
                             : "=r"(bf[ni][0]), "=r"(bf[ni][1])
                             : "r"(b_addr[ni] + boff + ks * 32));
#pragma unroll
            for (int mi = 0; mi < 4; mi++)
#pragma unroll
                for (int ni = 0; ni < 4; ni++)
                    mma8(acc[mi][ni], af[mi], bf[ni][0], bf[ni][1]);
        }

        if (it + 1 < iters) {
            uint32_t* As = sh + (cur ^ 1) * BUFE;
            uint32_t* Bs = As + 128 * SA;
#pragma unroll
            for (int rr = 0; rr < 4; rr++) {
                uint4 av = make_uint4(cvt_tf32(ra[rr][0]), cvt_tf32(ra[rr][1]),
                                      cvt_tf32(ra[rr][2]), cvt_tf32(ra[rr][3]));
                *(uint4*)&As[(lr + 32 * rr) * SA + lc] = av;
                uint4 bv = make_uint4(cvt_tf32(rb[rr][0]), cvt_tf32(rb[rr][1]),
                                      cvt_tf32(rb[rr][2]), cvt_tf32(rb[rr][3]));
                *(uint4*)&Bs[(lr + 32 * rr) * SA + lc] = bv;
            }
            __syncthreads();
        }
    }

    int g = lane >> 2, tg = lane & 3;
#pragma unroll
    for (int mi = 0; mi < 4; mi++) {
#pragma unroll
        for (int ni = 0; ni < 4; ni++) {
            int row = m0 + warp_m * 64 + mi * 16 + g;
            int col = n0 + warp_n * 32 + ni * 8 + tg * 2;
            *(float2*)&C[(size_t)row * N + col] =
                make_float2(acc[mi][ni][0], acc[mi][ni][1]);
            *(float2*)&C[(size_t)(row + 8) * N + col] =
                make_float2(acc[mi][ni][2], acc[mi][ni][3]);
        }
    }
}

// ---------------- RoPE (interleaved pairs) ----------------
__global__ void rope_kernel(float* __restrict__ t, const float* __restrict__ cs,
                            const float* __restrict__ sn, int nh, int total)
{
    int idx = blockIdx.x * blockDim.x + threadIdx.x;
    if (idx >= total) return;
    int pr = idx & 63;
    int hh = (idx >> 6) % nh;
    int ss = idx / (64 * nh);
    float c  = cs[ss * 64 + pr];
    float si = sn[ss * 64 + pr];
    float2* p = (float2*)(t + ((size_t)ss * nh + hh) * HD + pr * 2);
    float2 ri = *p;
    float2 o;
    o.x = ri.x * c - ri.y * si;
    o.y = ri.x * si + ri.y * c;
    *p = o;
}

// ---------------- Tensor-core flash attention, causal, GQA --------------------
// BM=128 (8 warps x m16), BN=64, HD=128. TF32 mma; QK^T uses 3-term hi/lo
// compensation (fp32-level accuracy), PV single tf32.
// smem (floats): Qs 128x132 | Khi 64x132 | Klo 64x132 | VsT 128x68 | Ps 128x76
#define QS_O  0
#define KHI_O 16896
#define KLO_O 25344
#define VT_O  33792
#define PS_O  42496
#define ATT_SMEM_FLOATS 52224   // 208896 bytes

__global__ __launch_bounds__(256, 1) void attn_tc(const float* __restrict__ Q,
                                                  const float* __restrict__ Kg,
                                                  const float* __restrict__ Vg,
                                                  float* __restrict__ O)
{
    extern __shared__ float sm[];
    int tid = threadIdx.x, wid = tid >> 5, lane = tid & 31;
    int qt = (int)gridDim.x - 1 - (int)blockIdx.x;   // longest-first
    int h = blockIdx.y, kvh = h >> 2;
    int qm0 = qt * 128;
    const float scale = 0.08838834764831845f;   // 1/sqrt(128)
    int g = lane >> 2, tg = lane & 3;
    int wr0 = wid * 16;
    int row0 = qm0 + wr0 + g, row1 = row0 + 8;

    // load Q tile (scaled), raw fp32
    for (int i = tid; i < 128 * 32; i += 256) {
        int r = i >> 5, c4 = (i & 31) << 2;
        float4 qv = *(const float4*)&Q[((size_t)(qm0 + r) * NH + h) * HD + c4];
        qv.x *= scale; qv.y *= scale; qv.z *= scale; qv.w *= scale;
        *(float4*)&sm[QS_O + r * 132 + c4] = qv;
    }

    uint32_t shb = (uint32_t)__cvta_generic_to_shared(sm);
    int la = lane & 15, ahi = lane >> 4;
    int rb = (lane & 7) + ((lane >> 4) << 3);
    int bhi = (lane >> 3) & 1;
    uint32_t aQ  = shb + (uint32_t)((QS_O  + (wr0 + la) * 132 + ahi * 4) << 2);
    uint32_t aP  = shb + (uint32_t)((PS_O  + (wr0 + la) * 76  + ahi * 4) << 2);
    uint32_t bKh = shb + (uint32_t)((KHI_O + rb * 132 + bhi * 4) << 2);
    uint32_t bKl = shb + (uint32_t)((KLO_O + rb * 132 + bhi * 4) << 2);
    uint32_t bV  = shb + (uint32_t)((VT_O  + rb * 68  + bhi * 4) << 2);

    float oa[16][4];
#pragma unroll
    for (int i = 0; i < 16; i++)
#pragma unroll
        for (int j = 0; j < 4; j++) oa[i][j] = 0.0f;
    float m0 = -1e30f, m1 = -1e30f, l0 = 0.0f, l1 = 0.0f;

    int ktmax = 2 * qt + 1;
    for (int kt = 0; kt <= ktmax; kt++) {
        int kn0 = kt * 64;
        __syncthreads();
        // load K (split hi/lo) and V (transposed, tf32)
        for (int i = tid; i < 64 * 32; i += 256) {
            int r = i >> 5, c4 = (i & 31) << 2;
            const float* kp = &Kg[((size_t)(kn0 + r) * NKV + kvh) * HD + c4];
            float4 kv = *(const float4*)kp;
            float hx = tf32f(kv.x), hy = tf32f(kv.y), hz = tf32f(kv.z), hw = tf32f(kv.w);
            *(float4*)&sm[KHI_O + r * 132 + c4] = make_float4(hx, hy, hz, hw);
            *(float4*)&sm[KLO_O + r * 132 + c4] =
                make_float4(tf32f(kv.x - hx), tf32f(kv.y - hy),
                            tf32f(kv.z - hz), tf32f(kv.w - hw));
            const float* vp = &Vg[((size_t)(kn0 + r) * NKV + kvh) * HD + c4];
            float4 vv = *(const float4*)vp;
            sm[VT_O + (c4 + 0) * 68 + r] = tf32f(vv.x);
            sm[VT_O + (c4 + 1) * 68 + r] = tf32f(vv.y);
            sm[VT_O + (c4 + 2) * 68 + r] = tf32f(vv.z);
            sm[VT_O + (c4 + 3) * 68 + r] = tf32f(vv.w);
        }
        __syncthreads();

        if (qm0 + wr0 + 15 < kn0) continue;   // warp fully masked (kt==2qt+1, wid<4)

        // ---- QK^T with 3-term tf32 compensation ----
        float sc[8][4];
#pragma unroll
        for (int i = 0; i < 8; i++)
#pragma unroll
            for (int j = 0; j < 4; j++) sc[i][j] = 0.0f;

#pragma unroll 2
        for (int ks = 0; ks < 16; ks++) {
            uint32_t ar[4];
            ldm4(ar, aQ + ks * 32);
            uint32_t ah[4], al[4];
#pragma unroll
            for (int j = 0; j < 4; j++) {
                float av = __uint_as_float(ar[j]);
                float hv = tf32f(av);
                ah[j] = __float_as_uint(hv);
                al[j] = cvt_tf32(av - hv);
            }
#pragma unroll
            for (int np = 0; np < 4; np++) {
                uint32_t bh[4], bl[4];
                ldm4(bh, bKh + (uint32_t)(np * 16 * 132 * 4) + ks * 32);
                ldm4(bl, bKl + (uint32_t)(np * 16 * 132 * 4) + ks * 32);
                mma8(sc[2 * np],     ah, bh[0], bh[1]);
                mma8(sc[2 * np],     al, bh[0], bh[1]);
                mma8(sc[2 * np],     ah, bl[0], bl[1]);
                mma8(sc[2 * np + 1], ah, bh[2], bh[3]);
                mma8(sc[2 * np + 1], al, bh[2], bh[3]);
                mma8(sc[2 * np + 1], ah, bl[2], bl[3]);
            }
        }

        // causal mask on diagonal tiles
        if (kt >= 2 * qt) {
#pragma unroll
            for (int nf = 0; nf < 8; nf++) {
                int kc = kn0 + nf * 8 + 2 * tg;
                if (kc > row0)     sc[nf][0] = -1e30f;
                if (kc + 1 > row0) sc[nf][1] = -1e30f;
                if (kc > row1)     sc[nf][2] = -1e30f;
                if (kc + 1 > row1) sc[nf][3] = -1e30f;
            }
        }

        // ---- online softmax (rows g and g+8) ----
        float rm0 = -1e30f, rm1 = -1e30f;
#pragma unroll
        for (int nf = 0; nf < 8; nf++) {
            rm0 = fmaxf(rm0, fmaxf(sc[nf][0], sc[nf][1]));
            rm1 = fmaxf(rm1, fmaxf(sc[nf][2], sc[nf][3]));
        }
        rm0 = fmaxf(rm0, __shfl_xor_sync(0xffffffffu, rm0, 1));
        rm0 = fmaxf(rm0, __shfl_xor_sync(0xffffffffu, rm0, 2));
        rm1 = fmaxf(rm1, __shfl_xor_sync(0xffffffffu, rm1, 1));
        rm1 = fmaxf(rm1, __shfl_xor_sync(0xffffffffu, rm1, 2));
        float mn0 = fmaxf(m0, rm0), mn1 = fmaxf(m1, rm1);
        float fac0 = __expf(m0 - mn0), fac1 = __expf(m1 - mn1);
        float rs0 = 0.0f, rs1 = 0.0f;
#pragma unroll
        for (int nf = 0; nf < 8; nf++) {
            sc[nf][0] = __expf(sc[nf][0] - mn0);
            sc[nf][1] = __expf(sc[nf][1] - mn0);
            sc[nf][2] = __expf(sc[nf][2] - mn1);
            sc[nf][3] = __expf(sc[nf][3] - mn1);
            rs0 += sc[nf][0] + sc[nf][1];
            rs1 += sc[nf][2] + sc[nf][3];
        }
        rs0 += __shfl_xor_sync(0xffffffffu, rs0, 1);
        rs0 += __shfl_xor_sync(0xffffffffu, rs0, 2);
        rs1 += __shfl_xor_sync(0xffffffffu, rs1, 1);
        rs1 += __shfl_xor_sync(0xffffffffu, rs1, 2);
        l0 = l0 * fac0 + rs0; m0 = mn0;
        l1 = l1 * fac1 + rs1; m1 = mn1;
#pragma unroll
        for (int nf = 0; nf < 16; nf++) {
            oa[nf][0] *= fac0; oa[nf][1] *= fac0;
            oa[nf][2] *= fac1; oa[nf][3] *= fac1;
        }

        // write P (tf32) to warp-private smem rows
        __syncwarp();
#pragma unroll
        for (int nf = 0; nf < 8; nf++) {
            *(float2*)&sm[PS_O + (wr0 + g) * 76 + nf * 8 + 2 * tg] =
                make_float2(tf32f(sc[nf][0]), tf32f(sc[nf][1]));
            *(float2*)&sm[PS_O + (wr0 + g + 8) * 76 + nf * 8 + 2 * tg] =
                make_float2(tf32f(sc[nf][2]), tf32f(sc[nf][3]));
        }
        __syncwarp();

        // ---- O += P @ V ----
#pragma unroll 2
        for (int ks2 = 0; ks2 < 8; ks2++) {
            uint32_t pa[4];
            ldm4(pa, aP + ks2 * 32);
#pragma unroll
            for (int np = 0; np < 8; np++) {
                uint32_t bv[4];
                ldm4(bv, bV + (uint32_t)(np * 16 * 68 * 4) + ks2 * 32);
                mma8(oa[2 * np],     pa, bv[0], bv[1]);
                mma8(oa[2 * np + 1], pa, bv[2], bv[3]);
            }
        }
    }

    // epilogue
    float inv0 = 1.0f / l0, inv1 = 1.0f / l1;
#pragma unroll
    for (int nf = 0; nf < 16; nf++) {
        int col = nf * 8 + 2 * tg;
        *(float2*)&O[((size_t)row0 * NH + h) * HD + col] =
            make_float2(oa[nf][0] * inv0, oa[nf][1] * inv0);
        *(float2*)&O[((size_t)row1 * NH + h) * HD + col] =
            make_float2(oa[nf][2] * inv1, oa[nf][3] * inv1);
    }
}

// ---------------- launch ----------------
extern "C" void kernel_launch(void* const* d_in, const int* in_sizes, int n_in,
                              void* d_out, int out_size)
{
    const float* x  = (const float*)d_in[0];
    const float* wq = (const float*)d_in[1];
    const float* wk = (const float*)d_in[2];
    const float* wv = (const float*)d_in[3];
    const float* wo = (const float*)d_in[4];
    const float* fc = (const float*)d_in[5];
    const float* fs = (const float*)d_in[6];
    float* out = (float*)d_out;

    float *q, *k, *v, *att;
    cudaGetSymbolAddress((void**)&q,   g_q);
    cudaGetSymbolAddress((void**)&k,   g_k);
    cudaGetSymbolAddress((void**)&v,   g_v);
    cudaGetSymbolAddress((void**)&att, g_att);

    int gsh = 2 * BUFE * (int)sizeof(uint32_t);
    cudaFuncSetAttribute(gemm_tf32, cudaFuncAttributeMaxDynamicSharedMemorySize, gsh);

    dim3 blk(256);
    gemm_tf32<<<dim3(DIM / 128, SEQ / 128), blk, gsh>>>(x, wq, q, SEQ, DIM, DIM);
    gemm_tf32<<<dim3(NKV * HD / 128, SEQ / 128), blk, gsh>>>(x, wk, k, SEQ, NKV * HD, DIM);
    gemm_tf32<<<dim3(NKV * HD / 128, SEQ / 128), blk, gsh>>>(x, wv, v, SEQ, NKV * HD, DIM);

    rope_kernel<<<(SEQ * NH * 64 + 255) / 256, 256>>>(q, fc, fs, NH, SEQ * NH * 64);
    rope_kernel<<<(SEQ * NKV * 64 + 255) / 256, 256>>>(k, fc, fs, NKV, SEQ * NKV * 64);

    int ash = ATT_SMEM_FLOATS * (int)sizeof(float);   // 208896
    cudaFuncSetAttribute(attn_tc, cudaFuncAttributeMaxDynamicSharedMemorySize, ash);
    attn_tc<<<dim3(SEQ / 128, NH), blk, ash>>>(q, k, v, att);

    gemm_tf32<<<dim3(DIM / 128, SEQ / 128), blk, gsh>>>(att, wo, out, SEQ, DIM, DIM);
}